// round 13
// baseline (speedup 1.0000x reference)
#include <cuda_runtime.h>
#include <cuda_bf16.h>
#include <cstdint>
#include <cstddef>

#define B_    64
#define T_    512
#define TS_   128     // rnn/gemm time slice
#define H_    256
#define G4    1024
#define KIN   768
#define CLUSTER 8
#define NB    4
#define JS    32
#define RROWS 128

#define KC    32
#define NCH   24
#define NSTG  2
#define ROWB  80
#define TILE_B (128 * ROWB)
#define STG_B  (4 * TILE_B)
#define GSM_TOTAL (NSTG * STG_B)   // 81920

// ---------------- scratch ----------------
__device__ float g_gp[(size_t)B_ * T_ * G4];
__device__ float g_sp[B_ * T_ * 2];
__device__ float g_bias[G4];
__device__ float g_tagc[3 * G4];
__device__ float g_h[B_ * H_];
__device__ float g_c[B_ * H_];
__device__ int   g_pred[B_];
__device__ __align__(16) __nv_bfloat16 g_Ahi[(size_t)B_ * T_ * KIN];
__device__ __align__(16) __nv_bfloat16 g_Alo[(size_t)B_ * T_ * KIN];
__device__ __align__(16) __nv_bfloat16 g_Bhi[G4 * KIN];
__device__ __align__(16) __nv_bfloat16 g_Blo[G4 * KIN];

// ---------------- PTX helpers (base sm_103 only) ----------------
__device__ __forceinline__ uint32_t smem_u32(const void* p) {
    uint32_t a;
    asm("{ .reg .u64 t; cvta.to.shared.u64 t, %1; cvt.u32.u64 %0, t; }" : "=r"(a) : "l"(p));
    return a;
}
__device__ __forceinline__ uint32_t ctarank_() {
    uint32_t r; asm("mov.u32 %0, %%cluster_ctarank;" : "=r"(r)); return r;
}
__device__ __forceinline__ void cluster_sync_() {
    asm volatile("barrier.cluster.arrive.aligned;\n\tbarrier.cluster.wait.aligned;" ::: "memory");
}
__device__ __forceinline__ void st_cluster_v4(uint32_t saddr, uint32_t dst,
                                              uint32_t a, uint32_t b,
                                              uint32_t c, uint32_t d) {
    asm volatile(
        "{\n\t.reg .b32 ra;\n\t"
        "mapa.shared::cluster.u32 ra, %0, %1;\n\t"
        "st.shared::cluster.v4.b32 [ra], {%2,%3,%4,%5};\n\t}"
        :: "r"(saddr), "r"(dst), "r"(a), "r"(b), "r"(c), "r"(d) : "memory");
}
__device__ __forceinline__ void cp16(uint32_t dst, const void* src) {
    asm volatile("cp.async.cg.shared.global [%0], [%1], 16;" :: "r"(dst), "l"(src));
}
#define CP_COMMIT() asm volatile("cp.async.commit_group;" ::: "memory")
#define CP_WAIT1()  asm volatile("cp.async.wait_group 1;" ::: "memory")
#define CP_WAIT0()  asm volatile("cp.async.wait_group 0;" ::: "memory")

__device__ __forceinline__ void ldsm4(uint32_t* r, uint32_t addr) {
    asm volatile("ldmatrix.sync.aligned.m8n8.x4.shared.b16 {%0,%1,%2,%3}, [%4];"
                 : "=r"(r[0]), "=r"(r[1]), "=r"(r[2]), "=r"(r[3]) : "r"(addr));
}
__device__ __forceinline__ void mma16816(float* c, const uint32_t* a, const uint32_t* b) {
    asm volatile(
        "mma.sync.aligned.m16n8k16.row.col.f32.bf16.bf16.f32 "
        "{%0,%1,%2,%3}, {%4,%5,%6,%7}, {%8,%9}, {%0,%1,%2,%3};"
        : "+f"(c[0]), "+f"(c[1]), "+f"(c[2]), "+f"(c[3])
        : "r"(a[0]), "r"(a[1]), "r"(a[2]), "r"(a[3]), "r"(b[0]), "r"(b[1]));
}
__device__ __forceinline__ void fma2(unsigned long long& d, unsigned long long a,
                                     unsigned long long b) {
    asm("fma.rn.f32x2 %0, %1, %2, %0;" : "+l"(d) : "l"(a), "l"(b));
}
__device__ __forceinline__ float2 unpack64(unsigned long long v) {
    float2 r;
    asm("mov.b64 {%0, %1}, %2;" : "=f"(r.x), "=f"(r.y) : "l"(v));
    return r;
}

// ---------------- fused prep: convA + convB + bias/tagc + rnn state init ----------------
#define NBLK_A 24576
#define NBLK_B 768
#define NBLK_P 4
#define NBLK_S 129
__global__ __launch_bounds__(256) void conv_fused_kernel(
    const float* __restrict__ A, const float* __restrict__ Wih,
    const float* __restrict__ bih, const float* __restrict__ bhh,
    const float* __restrict__ tag_em) {
    const int bid = blockIdx.x;
    if (bid < NBLK_A) {
        size_t i4 = (size_t)bid * 256 + threadIdx.x;
        float4 v = *(const float4*)(A + i4 * 4);
        __nv_bfloat16 hx = __float2bfloat16_rn(v.x), hy = __float2bfloat16_rn(v.y);
        __nv_bfloat16 hz = __float2bfloat16_rn(v.z), hw = __float2bfloat16_rn(v.w);
        __nv_bfloat16 lx = __float2bfloat16_rn(v.x - __bfloat162float(hx));
        __nv_bfloat16 ly = __float2bfloat16_rn(v.y - __bfloat162float(hy));
        __nv_bfloat16 lz = __float2bfloat16_rn(v.z - __bfloat162float(hz));
        __nv_bfloat16 lw = __float2bfloat16_rn(v.w - __bfloat162float(hw));
        __nv_bfloat16 hv[4] = {hx, hy, hz, hw};
        __nv_bfloat16 lv[4] = {lx, ly, lz, lw};
        ((uint2*)g_Ahi)[i4] = *(uint2*)hv;
        ((uint2*)g_Alo)[i4] = *(uint2*)lv;
    } else if (bid < NBLK_A + NBLK_B) {
        size_t i4 = (size_t)(bid - NBLK_A) * 256 + threadIdx.x;
        size_t e = i4 * 4;
        int n = (int)(e / KIN), k = (int)(e % KIN);
        float4 v = *(const float4*)(Wih + (size_t)n * 800 + 32 + k);
        __nv_bfloat16 hx = __float2bfloat16_rn(v.x), hy = __float2bfloat16_rn(v.y);
        __nv_bfloat16 hz = __float2bfloat16_rn(v.z), hw = __float2bfloat16_rn(v.w);
        __nv_bfloat16 lx = __float2bfloat16_rn(v.x - __bfloat162float(hx));
        __nv_bfloat16 ly = __float2bfloat16_rn(v.y - __bfloat162float(hy));
        __nv_bfloat16 lz = __float2bfloat16_rn(v.z - __bfloat162float(hz));
        __nv_bfloat16 lw = __float2bfloat16_rn(v.w - __bfloat162float(hw));
        __nv_bfloat16 hv[4] = {hx, hy, hz, hw};
        __nv_bfloat16 lv[4] = {lx, ly, lz, lw};
        ((uint2*)g_Bhi)[i4] = *(uint2*)hv;
        ((uint2*)g_Blo)[i4] = *(uint2*)lv;
    } else if (bid < NBLK_A + NBLK_B + NBLK_P) {
        int n = (bid - NBLK_A - NBLK_B) * 256 + threadIdx.x;
        if (n >= G4) return;
        g_bias[n] = bih[n] + bhh[n];
        float t0 = 0.f, t1 = 0.f;
        #pragma unroll
        for (int e = 0; e < 32; ++e) {
            float w = Wih[n * 800 + e];
            t0 = fmaf(tag_em[e], w, t0);
            t1 = fmaf(tag_em[32 + e], w, t1);
        }
        g_tagc[n] = t0;
        g_tagc[G4 + n] = t1;
        g_tagc[2 * G4 + n] = 0.f;
    } else {
        int sid = bid - NBLK_A - NBLK_B - NBLK_P;
        if (sid < 64) g_h[sid * 256 + threadIdx.x] = 0.f;
        else if (sid < 128) g_c[(sid - 64) * 256 + threadIdx.x] = 0.f;
        else if (threadIdx.x < B_) g_pred[threadIdx.x] = 2;
    }
}

// ---------------- HMMA GEMM, t-sliced: bm = blockIdx.y*4 + q ----------------
__global__ __launch_bounds__(256, 2) void gemm_kernel(int q) {
    extern __shared__ char smem[];
    const uint32_t sb = smem_u32(smem);
    const int tid = threadIdx.x;
    const int wid = tid >> 5, lane = tid & 31;
    const int bn = blockIdx.x, bm = blockIdx.y * 4 + q;
    const int m0 = bm * 128, n0 = bn * 128;
    const int wm = (wid & 1) * 64;
    const int wn = (wid >> 1) * 32;

    const __nv_bfloat16* srcp[8];
    uint32_t dsto[8];
    #pragma unroll
    for (int i = 0; i < 8; ++i) {
        int id = tid + i * 256;
        int tile = id >> 9, rem = id & 511;
        int row = rem >> 2, c4 = rem & 3;
        const __nv_bfloat16* base =
            (tile == 0) ? g_Ahi + (size_t)m0 * KIN :
            (tile == 1) ? g_Alo + (size_t)m0 * KIN :
            (tile == 2) ? g_Bhi + (size_t)n0 * KIN :
                          g_Blo + (size_t)n0 * KIN;
        srcp[i] = base + (size_t)row * KIN + c4 * 8;
        dsto[i] = (uint32_t)(tile * TILE_B + row * ROWB + c4 * 16);
    }

    float acc[4][4][4];
    #pragma unroll
    for (int a = 0; a < 4; ++a)
        #pragma unroll
        for (int b = 0; b < 4; ++b)
            #pragma unroll
            for (int qq = 0; qq < 4; ++qq) acc[a][b][qq] = 0.f;

    const uint32_t aoff = (uint32_t)((wm + (lane & 15)) * ROWB + (lane >> 4) * 16);
    const int brow = ((lane >> 4) & 1) * 8 + (lane & 7);
    const uint32_t boff = (uint32_t)((wn + brow) * ROWB + ((lane >> 3) & 1) * 16);

    #pragma unroll
    for (int i = 0; i < 8; ++i) cp16(sb + dsto[i], srcp[i]);
    CP_COMMIT();

    for (int c = 0; c < NCH; ++c) {
        if (c + 1 < NCH) {
            uint32_t stg = sb + (uint32_t)((c + 1) & 1) * STG_B;
            #pragma unroll
            for (int i = 0; i < 8; ++i) cp16(stg + dsto[i], srcp[i] + (c + 1) * KC);
            CP_COMMIT();
            CP_WAIT1();
        } else {
            CP_WAIT0();
        }
        __syncthreads();

        const uint32_t sbase = sb + (uint32_t)(c & 1) * STG_B;
        const uint32_t sAhi = sbase, sAlo = sbase + TILE_B;
        const uint32_t sBhi = sbase + 2 * TILE_B, sBlo = sbase + 3 * TILE_B;

        #pragma unroll
        for (int ks = 0; ks < 2; ++ks) {
            const uint32_t ko = ks * 32;
            uint32_t ah[4][4], bh[2][4], bl[2][4];
            #pragma unroll
            for (int mi = 0; mi < 4; ++mi) ldsm4(ah[mi], sAhi + aoff + mi * 16 * ROWB + ko);
            #pragma unroll
            for (int nj = 0; nj < 2; ++nj) ldsm4(bh[nj], sBhi + boff + nj * 16 * ROWB + ko);
            #pragma unroll
            for (int mi = 0; mi < 4; ++mi)
                #pragma unroll
                for (int ni = 0; ni < 4; ++ni)
                    mma16816(acc[mi][ni], ah[mi], &bh[ni >> 1][(ni & 1) * 2]);
            #pragma unroll
            for (int nj = 0; nj < 2; ++nj) ldsm4(bl[nj], sBlo + boff + nj * 16 * ROWB + ko);
            #pragma unroll
            for (int mi = 0; mi < 4; ++mi)
                #pragma unroll
                for (int ni = 0; ni < 4; ++ni)
                    mma16816(acc[mi][ni], ah[mi], &bl[ni >> 1][(ni & 1) * 2]);
            #pragma unroll
            for (int mi = 0; mi < 4; ++mi) ldsm4(ah[mi], sAlo + aoff + mi * 16 * ROWB + ko);
            #pragma unroll
            for (int mi = 0; mi < 4; ++mi)
                #pragma unroll
                for (int ni = 0; ni < 4; ++ni)
                    mma16816(acc[mi][ni], ah[mi], &bh[ni >> 1][(ni & 1) * 2]);
        }
        __syncthreads();
    }

    const int rowb2 = lane >> 2, col2 = (lane & 3) * 2;
    #pragma unroll
    for (int mi = 0; mi < 4; ++mi) {
        const int gr = m0 + wm + mi * 16 + rowb2;
        #pragma unroll
        for (int ni = 0; ni < 4; ++ni) {
            const int gc = n0 + wn + ni * 8 + col2;
            float b0v = __ldg(&g_bias[gc]), b1v = __ldg(&g_bias[gc + 1]);
            float2 v0 = make_float2(acc[mi][ni][0] + b0v, acc[mi][ni][1] + b1v);
            float2 v1 = make_float2(acc[mi][ni][2] + b0v, acc[mi][ni][3] + b1v);
            *(float2*)&g_gp[(size_t)gr * G4 + gc] = v0;
            *(float2*)&g_gp[(size_t)(gr + 8) * G4 + gc] = v1;
        }
    }
}

// ---------------- score_pre ----------------
__global__ __launch_bounds__(256) void spre_kernel(const float* __restrict__ sents,
                                                   const float* __restrict__ Waff,
                                                   const float* __restrict__ baff) {
    int warp = (blockIdx.x * 256 + threadIdx.x) >> 5;
    int lane = threadIdx.x & 31;
    if (warp >= B_ * T_) return;
    const float4* a  = (const float4*)(sents + (size_t)warp * KIN);
    const float4* w0 = (const float4*)(Waff + 256);
    const float4* w1 = (const float4*)(Waff + G4 + 256);
    float s0 = 0.f, s1 = 0.f;
    #pragma unroll
    for (int i = lane; i < KIN / 4; i += 32) {
        float4 av = a[i], v0 = w0[i], v1 = w1[i];
        s0 = fmaf(av.x, v0.x, s0); s0 = fmaf(av.y, v0.y, s0);
        s0 = fmaf(av.z, v0.z, s0); s0 = fmaf(av.w, v0.w, s0);
        s1 = fmaf(av.x, v1.x, s1); s1 = fmaf(av.y, v1.y, s1);
        s1 = fmaf(av.z, v1.z, s1); s1 = fmaf(av.w, v1.w, s1);
    }
    #pragma unroll
    for (int o = 16; o > 0; o >>= 1) {
        s0 += __shfl_xor_sync(0xffffffffu, s0, o);
        s1 += __shfl_xor_sync(0xffffffffu, s1, o);
    }
    if (lane == 0) {
        g_sp[(size_t)warp * 2]     = s0 + baff[0];
        g_sp[(size_t)warp * 2 + 1] = s1 + baff[1];
    }
}

// ---------------- recurrence: R9 structure, t-sliced with gmem state handoff ----------------
struct RnnSmem {
    float hbuf[2][NB][H_];     // offset 0; double-buffered MASKED h (16B aligned)
    float part[2][128][NB];
    float tagc[3][RROWS];
    float waffh[2][H_];
    float maskS[NB][T_];
    float hstage[NB * JS];
    float scstage[8];
    float scp[2][8][8];
    int   pred[NB];
};

__device__ __forceinline__ float sigf(float x) {
    return __fdividef(1.f, 1.f + __expf(-x));
}
__device__ __forceinline__ float tanhfast(float x) {
    float e = __expf(2.f * x);
    return 1.f - __fdividef(2.f, e + 1.f);
}

__global__ void __cluster_dims__(CLUSTER, 1, 1) __launch_bounds__(256, 1)
rnn_kernel(const float* __restrict__ mask,
           const float* __restrict__ Whh,
           const float* __restrict__ Waff,
           float* __restrict__ out,
           int t0) {
    extern __shared__ unsigned char smem_raw[];
    RnnSmem& s = *reinterpret_cast<RnnSmem*>(smem_raw);

    const int tid = threadIdx.x;
    const uint32_t rank = ctarank_();
    const int cid = blockIdx.x >> 3;
    const int bbase = cid * NB;

    const int r = tid & 127;
    const int half = tid >> 7;
    const int grow = (r >> 5) * 256 + (int)rank * JS + (r & 31);

    ulonglong2 wreg2[32];
    {
        const ulonglong2* wsrc = (const ulonglong2*)(Whh + (size_t)grow * H_ + half * 128);
        #pragma unroll
        for (int i = 0; i < 32; ++i) wreg2[i] = wsrc[i];
    }

    for (int rr = tid; rr < RROWS; rr += 256) {
        int gr = (rr >> 5) * 256 + (int)rank * JS + (rr & 31);
        s.tagc[0][rr] = g_tagc[gr];
        s.tagc[1][rr] = g_tagc[G4 + gr];
        s.tagc[2][rr] = 0.f;
    }
    for (int i = tid; i < 2 * H_; i += 256) s.waffh[i >> 8][i & 255] = Waff[(i >> 8) * G4 + (i & 255)];
    // load carried h state into hbuf[0]  (t0 is even, so first step reads parity 0)
    for (int i = tid; i < NB * H_; i += 256)
        s.hbuf[0][i >> 8][i & 255] = g_h[(bbase + (i >> 8)) * H_ + (i & 255)];
    for (int i = tid; i < NB * T_; i += 256)
        s.maskS[i >> 9][i & 511] = mask[(size_t)(bbase + (i >> 9)) * T_ + (i & 511)];
    if (tid < NB) s.pred[tid] = g_pred[bbase + tid];
    __syncthreads();

    const int eb = tid >> 5, ej = tid & 31;    // phase-2 identity (tid < 128)
    float c_reg = 0.f;
    if (tid < 128) c_reg = g_c[(bbase + eb) * H_ + (int)rank * JS + ej];

    const int pdst = tid & 7;
    const int pchunk = tid >> 3;
    const int pe = pchunk * 4;
    const int peb = pe >> 5, pej = pe & 31;

    size_t gbase = 0;
    if (tid < 128)
        gbase = ((size_t)(bbase + eb) * T_) * G4 + (int)rank * JS + ej;
    float gpn[4];
    if (tid < 128) {
        #pragma unroll
        for (int g = 0; g < 4; ++g) gpn[g] = __ldg(&g_gp[gbase + (size_t)t0 * G4 + g * 256]);
    }
    const size_t spbase = (size_t)(bbase + (tid & 3)) * T_ * 2;
    float spn0 = 0.f, spn1 = 0.f;
    if (tid < NB) {
        spn0 = __ldg(&g_sp[spbase + (size_t)t0 * 2]);
        spn1 = __ldg(&g_sp[spbase + (size_t)t0 * 2 + 1]);
    }

    const int tend = t0 + TS_;
    for (int t = t0; t < tend; ++t) {
        const int par = t & 1;

        float gp[4];
        if (tid < 128) {
            #pragma unroll
            for (int g = 0; g < 4; ++g) gp[g] = gpn[g];
            if (t + 1 < T_) {
                const size_t gb = gbase + (size_t)(t + 1) * G4;
                #pragma unroll
                for (int g = 0; g < 4; ++g) gpn[g] = __ldg(&g_gp[gb + g * 256]);
            }
        }
        float sp0 = spn0, sp1 = spn1;
        if (tid < NB && t + 1 < T_) {
            spn0 = __ldg(&g_sp[spbase + (size_t)(t + 1) * 2]);
            spn1 = __ldg(&g_sp[spbase + (size_t)(t + 1) * 2 + 1]);
        }

        // ---- phase 1: matvec partials via packed f32x2 (reads hbuf[par]) ----
        float a2[NB];
        #pragma unroll
        for (int b = 0; b < NB; ++b) {
            const ulonglong2* x2 = (const ulonglong2*)&s.hbuf[par][b][half * 128];
            unsigned long long acc0 = 0ULL, acc1 = 0ULL;
            #pragma unroll
            for (int i = 0; i < 32; ++i) {
                ulonglong2 w = wreg2[i];
                ulonglong2 xv = x2[i];
                fma2(acc0, w.x, xv.x);
                fma2(acc1, w.y, xv.y);
            }
            float2 f0 = unpack64(acc0), f1 = unpack64(acc1);
            a2[b] = (f0.x + f0.y) + (f1.x + f1.y);
        }
        *(float4*)&s.part[half][r][0] = make_float4(a2[0], a2[1], a2[2], a2[3]);
        __syncthreads();   // A

        // ---- phase 2 (tid<128): gates, cell, masked h to stage, score partials ----
        if (tid < 128) {
            const int pd = s.pred[eb];
            float gate[4];
            #pragma unroll
            for (int g = 0; g < 4; ++g) {
                const int rr = g * 32 + ej;
                gate[g] = gp[g] + s.tagc[pd][rr] + s.part[0][rr][eb] + s.part[1][rr][eb];
            }
            float cn = sigf(gate[1]) * c_reg + sigf(gate[0]) * tanhfast(gate[2]);
            float hn = sigf(gate[3]) * tanhfast(cn);
            float mi = s.maskS[eb][t];
            c_reg = mi * cn + (1.f - mi) * c_reg;
            float hold = s.hbuf[par][eb][(int)rank * JS + ej];
            s.hstage[eb * JS + ej] = mi * hn + (1.f - mi) * hold;
            float p0 = hn * s.waffh[0][(int)rank * JS + ej];
            float p1 = hn * s.waffh[1][(int)rank * JS + ej];
            #pragma unroll
            for (int o = 16; o > 0; o >>= 1) {
                p0 += __shfl_xor_sync(0xffffffffu, p0, o);
                p1 += __shfl_xor_sync(0xffffffffu, p1, o);
            }
            if (ej == 0) {
                s.scstage[eb * 2]     = p0;
                s.scstage[eb * 2 + 1] = p1;
            }
        }
        __syncthreads();   // B

        // ---- push: vectorized remote stores ----
        {
            const uint4 hv = *(const uint4*)&s.hstage[pe];
            uint32_t daddr = (uint32_t)__cvta_generic_to_shared(
                &s.hbuf[par ^ 1][peb][(int)rank * JS + pej]);
            st_cluster_v4(daddr, (uint32_t)pdst, hv.x, hv.y, hv.z, hv.w);
            if (tid < 16) {
                const uint4 sv = *(const uint4*)&s.scstage[(tid >> 3) * 4];
                uint32_t saddr2 = (uint32_t)__cvta_generic_to_shared(
                    &s.scp[par][rank][(tid >> 3) * 4]);
                st_cluster_v4(saddr2, (uint32_t)pdst, sv.x, sv.y, sv.z, sv.w);
            }
        }
        cluster_sync_();   // C

        // ---- phase 3 (tid<4): sum score partials, pred, output ----
        if (tid < NB) {
            float s0 = sp0, s1 = sp1;
            #pragma unroll
            for (int src = 0; src < 8; ++src) {
                s0 += s.scp[par][src][tid * 2];
                s1 += s.scp[par][src][tid * 2 + 1];
            }
            s.pred[tid] = (s1 > s0) ? 1 : 0;
            if (rank == 0) {
                float mx = fmaxf(s0, s1);
                float lse = mx + __logf(__expf(s0 - mx) + __expf(s1 - mx));
                size_t o = ((size_t)(bbase + tid) * T_ + t) * 2;
                out[o]     = s0 - lse;
                out[o + 1] = s1 - lse;
            }
        }
    }

    // ---- state handoff: last push landed in hbuf[0] (tend-1 is odd) ----
    __syncthreads();
    if (tid < 128)
        g_c[(bbase + eb) * H_ + (int)rank * JS + ej] = c_reg;
    if (rank == 0) {
        for (int i = tid; i < NB * H_; i += 256)
            g_h[(bbase + (i >> 8)) * H_ + (i & 255)] = s.hbuf[0][i >> 8][i & 255];
        if (tid < NB) g_pred[bbase + tid] = s.pred[tid];
    }
    cluster_sync_();
}

// ---------------- launch: dual-stream overlap of gemm slices with rnn slices ----------------
extern "C" void kernel_launch(void* const* d_in, const int* in_sizes, int n_in,
                              void* d_out, int out_size) {
    const float* sents  = (const float*)d_in[0];
    const float* mask   = (const float*)d_in[1];
    const float* Wih    = (const float*)d_in[2];
    const float* Whh    = (const float*)d_in[3];
    const float* bih    = (const float*)d_in[4];
    const float* bhh    = (const float*)d_in[5];
    const float* Waff   = (const float*)d_in[6];
    const float* baff   = (const float*)d_in[7];
    const float* tag_em = (const float*)d_in[8];
    float* out = (float*)d_out;

    static cudaStream_t s2 = nullptr;
    static cudaEvent_t evC = nullptr, ev1 = nullptr, ev2 = nullptr, ev3 = nullptr;
    if (s2 == nullptr) {
        cudaStreamCreateWithFlags(&s2, cudaStreamNonBlocking);
        cudaEventCreateWithFlags(&evC, cudaEventDisableTiming);
        cudaEventCreateWithFlags(&ev1, cudaEventDisableTiming);
        cudaEventCreateWithFlags(&ev2, cudaEventDisableTiming);
        cudaEventCreateWithFlags(&ev3, cudaEventDisableTiming);
    }

    cudaFuncSetAttribute(gemm_kernel, cudaFuncAttributeMaxDynamicSharedMemorySize, GSM_TOTAL);
    cudaFuncSetAttribute(rnn_kernel, cudaFuncAttributeMaxDynamicSharedMemorySize,
                         (int)sizeof(RnnSmem));

    // main stream: prep + spre + gemm slice 0
    conv_fused_kernel<<<NBLK_A + NBLK_B + NBLK_P + NBLK_S, 256>>>(sents, Wih, bih, bhh, tag_em);
    cudaEventRecord(evC, 0);
    spre_kernel<<<(B_ * T_) / 8, 256>>>(sents, Waff, baff);
    gemm_kernel<<<dim3(G4 / 128, 64), 256, GSM_TOTAL>>>(0);

    // side stream: gemm slices 1-3 (depend only on conv)
    cudaStreamWaitEvent(s2, evC, 0);
    gemm_kernel<<<dim3(G4 / 128, 64), 256, GSM_TOTAL, s2>>>(1);
    cudaEventRecord(ev1, s2);
    gemm_kernel<<<dim3(G4 / 128, 64), 256, GSM_TOTAL, s2>>>(2);
    cudaEventRecord(ev2, s2);
    gemm_kernel<<<dim3(G4 / 128, 64), 256, GSM_TOTAL, s2>>>(3);
    cudaEventRecord(ev3, s2);

    // main stream: rnn slices, each gated on its gemm slice
    rnn_kernel<<<16 * CLUSTER, 256, sizeof(RnnSmem)>>>(mask, Whh, Waff, out, 0);
    cudaStreamWaitEvent(0, ev1, 0);
    rnn_kernel<<<16 * CLUSTER, 256, sizeof(RnnSmem)>>>(mask, Whh, Waff, out, 128);
    cudaStreamWaitEvent(0, ev2, 0);
    rnn_kernel<<<16 * CLUSTER, 256, sizeof(RnnSmem)>>>(mask, Whh, Waff, out, 256);
    cudaStreamWaitEvent(0, ev3, 0);
    rnn_kernel<<<16 * CLUSTER, 256, sizeof(RnnSmem)>>>(mask, Whh, Waff, out, 384);
}

// round 14
// speedup vs baseline: 1.0008x; 1.0008x over previous
#include <cuda_runtime.h>
#include <cuda_bf16.h>
#include <cstdint>
#include <cstddef>

#define B_    64
#define T_    512
#define TS_   128     // rnn/gemm time slice
#define H_    256
#define G4    1024
#define KIN   768
#define CLUSTER 8
#define NB    4
#define JS    32
#define RROWS 128

#define KC    32
#define NCH   24
#define NSTG  2
#define ROWB  80
#define TILE_B (128 * ROWB)
#define STG_B  (4 * TILE_B)
#define GSM_TOTAL (NSTG * STG_B)   // 81920

// ---------------- scratch ----------------
__device__ float g_gp[(size_t)B_ * T_ * G4];
__device__ float g_sp[B_ * T_ * 2];
__device__ float g_bias[G4];
__device__ float g_tagc[3 * G4];
__device__ float g_h[B_ * H_];
__device__ float g_c[B_ * H_];
__device__ int   g_pred[B_];
__device__ __align__(16) __nv_bfloat16 g_Ahi[(size_t)B_ * T_ * KIN];
__device__ __align__(16) __nv_bfloat16 g_Alo[(size_t)B_ * T_ * KIN];
__device__ __align__(16) __nv_bfloat16 g_Bhi[G4 * KIN];
__device__ __align__(16) __nv_bfloat16 g_Blo[G4 * KIN];

// ---------------- PTX helpers (base sm_103 only) ----------------
__device__ __forceinline__ uint32_t smem_u32(const void* p) {
    uint32_t a;
    asm("{ .reg .u64 t; cvta.to.shared.u64 t, %1; cvt.u32.u64 %0, t; }" : "=r"(a) : "l"(p));
    return a;
}
__device__ __forceinline__ uint32_t ctarank_() {
    uint32_t r; asm("mov.u32 %0, %%cluster_ctarank;" : "=r"(r)); return r;
}
__device__ __forceinline__ void cluster_sync_() {
    asm volatile("barrier.cluster.arrive.aligned;\n\tbarrier.cluster.wait.aligned;" ::: "memory");
}
__device__ __forceinline__ void st_cluster_v4(uint32_t saddr, uint32_t dst,
                                              uint32_t a, uint32_t b,
                                              uint32_t c, uint32_t d) {
    asm volatile(
        "{\n\t.reg .b32 ra;\n\t"
        "mapa.shared::cluster.u32 ra, %0, %1;\n\t"
        "st.shared::cluster.v4.b32 [ra], {%2,%3,%4,%5};\n\t}"
        :: "r"(saddr), "r"(dst), "r"(a), "r"(b), "r"(c), "r"(d) : "memory");
}
__device__ __forceinline__ void cp16(uint32_t dst, const void* src) {
    asm volatile("cp.async.cg.shared.global [%0], [%1], 16;" :: "r"(dst), "l"(src));
}
#define CP_COMMIT() asm volatile("cp.async.commit_group;" ::: "memory")
#define CP_WAIT1()  asm volatile("cp.async.wait_group 1;" ::: "memory")
#define CP_WAIT0()  asm volatile("cp.async.wait_group 0;" ::: "memory")

__device__ __forceinline__ void ldsm4(uint32_t* r, uint32_t addr) {
    asm volatile("ldmatrix.sync.aligned.m8n8.x4.shared.b16 {%0,%1,%2,%3}, [%4];"
                 : "=r"(r[0]), "=r"(r[1]), "=r"(r[2]), "=r"(r[3]) : "r"(addr));
}
__device__ __forceinline__ void mma16816(float* c, const uint32_t* a, const uint32_t* b) {
    asm volatile(
        "mma.sync.aligned.m16n8k16.row.col.f32.bf16.bf16.f32 "
        "{%0,%1,%2,%3}, {%4,%5,%6,%7}, {%8,%9}, {%0,%1,%2,%3};"
        : "+f"(c[0]), "+f"(c[1]), "+f"(c[2]), "+f"(c[3])
        : "r"(a[0]), "r"(a[1]), "r"(a[2]), "r"(a[3]), "r"(b[0]), "r"(b[1]));
}
__device__ __forceinline__ void fma2(unsigned long long& d, unsigned long long a,
                                     unsigned long long b) {
    asm("fma.rn.f32x2 %0, %1, %2, %0;" : "+l"(d) : "l"(a), "l"(b));
}
__device__ __forceinline__ float2 unpack64(unsigned long long v) {
    float2 r;
    asm("mov.b64 {%0, %1}, %2;" : "=f"(r.x), "=f"(r.y) : "l"(v));
    return r;
}

// ---------------- fused prep: convA + convB + bias/tagc + rnn state init ----------------
#define NBLK_A 24576
#define NBLK_B 768
#define NBLK_P 4
#define NBLK_S 129
__global__ __launch_bounds__(256) void conv_fused_kernel(
    const float* __restrict__ A, const float* __restrict__ Wih,
    const float* __restrict__ bih, const float* __restrict__ bhh,
    const float* __restrict__ tag_em) {
    const int bid = blockIdx.x;
    if (bid < NBLK_A) {
        size_t i4 = (size_t)bid * 256 + threadIdx.x;
        float4 v = *(const float4*)(A + i4 * 4);
        __nv_bfloat16 hx = __float2bfloat16_rn(v.x), hy = __float2bfloat16_rn(v.y);
        __nv_bfloat16 hz = __float2bfloat16_rn(v.z), hw = __float2bfloat16_rn(v.w);
        __nv_bfloat16 lx = __float2bfloat16_rn(v.x - __bfloat162float(hx));
        __nv_bfloat16 ly = __float2bfloat16_rn(v.y - __bfloat162float(hy));
        __nv_bfloat16 lz = __float2bfloat16_rn(v.z - __bfloat162float(hz));
        __nv_bfloat16 lw = __float2bfloat16_rn(v.w - __bfloat162float(hw));
        __nv_bfloat16 hv[4] = {hx, hy, hz, hw};
        __nv_bfloat16 lv[4] = {lx, ly, lz, lw};
        ((uint2*)g_Ahi)[i4] = *(uint2*)hv;
        ((uint2*)g_Alo)[i4] = *(uint2*)lv;
    } else if (bid < NBLK_A + NBLK_B) {
        size_t i4 = (size_t)(bid - NBLK_A) * 256 + threadIdx.x;
        size_t e = i4 * 4;
        int n = (int)(e / KIN), k = (int)(e % KIN);
        float4 v = *(const float4*)(Wih + (size_t)n * 800 + 32 + k);
        __nv_bfloat16 hx = __float2bfloat16_rn(v.x), hy = __float2bfloat16_rn(v.y);
        __nv_bfloat16 hz = __float2bfloat16_rn(v.z), hw = __float2bfloat16_rn(v.w);
        __nv_bfloat16 lx = __float2bfloat16_rn(v.x - __bfloat162float(hx));
        __nv_bfloat16 ly = __float2bfloat16_rn(v.y - __bfloat162float(hy));
        __nv_bfloat16 lz = __float2bfloat16_rn(v.z - __bfloat162float(hz));
        __nv_bfloat16 lw = __float2bfloat16_rn(v.w - __bfloat162float(hw));
        __nv_bfloat16 hv[4] = {hx, hy, hz, hw};
        __nv_bfloat16 lv[4] = {lx, ly, lz, lw};
        ((uint2*)g_Bhi)[i4] = *(uint2*)hv;
        ((uint2*)g_Blo)[i4] = *(uint2*)lv;
    } else if (bid < NBLK_A + NBLK_B + NBLK_P) {
        int n = (bid - NBLK_A - NBLK_B) * 256 + threadIdx.x;
        if (n >= G4) return;
        g_bias[n] = bih[n] + bhh[n];
        float t0 = 0.f, t1 = 0.f;
        #pragma unroll
        for (int e = 0; e < 32; ++e) {
            float w = Wih[n * 800 + e];
            t0 = fmaf(tag_em[e], w, t0);
            t1 = fmaf(tag_em[32 + e], w, t1);
        }
        g_tagc[n] = t0;
        g_tagc[G4 + n] = t1;
        g_tagc[2 * G4 + n] = 0.f;
    } else {
        int sid = bid - NBLK_A - NBLK_B - NBLK_P;
        if (sid < 64) g_h[sid * 256 + threadIdx.x] = 0.f;
        else if (sid < 128) g_c[(sid - 64) * 256 + threadIdx.x] = 0.f;
        else if (threadIdx.x < B_) g_pred[threadIdx.x] = 2;
    }
}

// ---------------- HMMA GEMM, t-sliced: bm = blockIdx.y*4 + q ----------------
__global__ __launch_bounds__(256, 2) void gemm_kernel(int q) {
    extern __shared__ char smem[];
    const uint32_t sb = smem_u32(smem);
    const int tid = threadIdx.x;
    const int wid = tid >> 5, lane = tid & 31;
    const int bn = blockIdx.x, bm = blockIdx.y * 4 + q;
    const int m0 = bm * 128, n0 = bn * 128;
    const int wm = (wid & 1) * 64;
    const int wn = (wid >> 1) * 32;

    const __nv_bfloat16* srcp[8];
    uint32_t dsto[8];
    #pragma unroll
    for (int i = 0; i < 8; ++i) {
        int id = tid + i * 256;
        int tile = id >> 9, rem = id & 511;
        int row = rem >> 2, c4 = rem & 3;
        const __nv_bfloat16* base =
            (tile == 0) ? g_Ahi + (size_t)m0 * KIN :
            (tile == 1) ? g_Alo + (size_t)m0 * KIN :
            (tile == 2) ? g_Bhi + (size_t)n0 * KIN :
                          g_Blo + (size_t)n0 * KIN;
        srcp[i] = base + (size_t)row * KIN + c4 * 8;
        dsto[i] = (uint32_t)(tile * TILE_B + row * ROWB + c4 * 16);
    }

    float acc[4][4][4];
    #pragma unroll
    for (int a = 0; a < 4; ++a)
        #pragma unroll
        for (int b = 0; b < 4; ++b)
            #pragma unroll
            for (int qq = 0; qq < 4; ++qq) acc[a][b][qq] = 0.f;

    const uint32_t aoff = (uint32_t)((wm + (lane & 15)) * ROWB + (lane >> 4) * 16);
    const int brow = ((lane >> 4) & 1) * 8 + (lane & 7);
    const uint32_t boff = (uint32_t)((wn + brow) * ROWB + ((lane >> 3) & 1) * 16);

    #pragma unroll
    for (int i = 0; i < 8; ++i) cp16(sb + dsto[i], srcp[i]);
    CP_COMMIT();

    for (int c = 0; c < NCH; ++c) {
        if (c + 1 < NCH) {
            uint32_t stg = sb + (uint32_t)((c + 1) & 1) * STG_B;
            #pragma unroll
            for (int i = 0; i < 8; ++i) cp16(stg + dsto[i], srcp[i] + (c + 1) * KC);
            CP_COMMIT();
            CP_WAIT1();
        } else {
            CP_WAIT0();
        }
        __syncthreads();

        const uint32_t sbase = sb + (uint32_t)(c & 1) * STG_B;
        const uint32_t sAhi = sbase, sAlo = sbase + TILE_B;
        const uint32_t sBhi = sbase + 2 * TILE_B, sBlo = sbase + 3 * TILE_B;

        #pragma unroll
        for (int ks = 0; ks < 2; ++ks) {
            const uint32_t ko = ks * 32;
            uint32_t ah[4][4], bh[2][4], bl[2][4];
            #pragma unroll
            for (int mi = 0; mi < 4; ++mi) ldsm4(ah[mi], sAhi + aoff + mi * 16 * ROWB + ko);
            #pragma unroll
            for (int nj = 0; nj < 2; ++nj) ldsm4(bh[nj], sBhi + boff + nj * 16 * ROWB + ko);
            #pragma unroll
            for (int mi = 0; mi < 4; ++mi)
                #pragma unroll
                for (int ni = 0; ni < 4; ++ni)
                    mma16816(acc[mi][ni], ah[mi], &bh[ni >> 1][(ni & 1) * 2]);
            #pragma unroll
            for (int nj = 0; nj < 2; ++nj) ldsm4(bl[nj], sBlo + boff + nj * 16 * ROWB + ko);
            #pragma unroll
            for (int mi = 0; mi < 4; ++mi)
                #pragma unroll
                for (int ni = 0; ni < 4; ++ni)
                    mma16816(acc[mi][ni], ah[mi], &bl[ni >> 1][(ni & 1) * 2]);
            #pragma unroll
            for (int mi = 0; mi < 4; ++mi) ldsm4(ah[mi], sAlo + aoff + mi * 16 * ROWB + ko);
            #pragma unroll
            for (int mi = 0; mi < 4; ++mi)
                #pragma unroll
                for (int ni = 0; ni < 4; ++ni)
                    mma16816(acc[mi][ni], ah[mi], &bh[ni >> 1][(ni & 1) * 2]);
        }
        __syncthreads();
    }

    const int rowb2 = lane >> 2, col2 = (lane & 3) * 2;
    #pragma unroll
    for (int mi = 0; mi < 4; ++mi) {
        const int gr = m0 + wm + mi * 16 + rowb2;
        #pragma unroll
        for (int ni = 0; ni < 4; ++ni) {
            const int gc = n0 + wn + ni * 8 + col2;
            float b0v = __ldg(&g_bias[gc]), b1v = __ldg(&g_bias[gc + 1]);
            float2 v0 = make_float2(acc[mi][ni][0] + b0v, acc[mi][ni][1] + b1v);
            float2 v1 = make_float2(acc[mi][ni][2] + b0v, acc[mi][ni][3] + b1v);
            *(float2*)&g_gp[(size_t)gr * G4 + gc] = v0;
            *(float2*)&g_gp[(size_t)(gr + 8) * G4 + gc] = v1;
        }
    }
}

// ---------------- score_pre ----------------
__global__ __launch_bounds__(256) void spre_kernel(const float* __restrict__ sents,
                                                   const float* __restrict__ Waff,
                                                   const float* __restrict__ baff) {
    int warp = (blockIdx.x * 256 + threadIdx.x) >> 5;
    int lane = threadIdx.x & 31;
    if (warp >= B_ * T_) return;
    const float4* a  = (const float4*)(sents + (size_t)warp * KIN);
    const float4* w0 = (const float4*)(Waff + 256);
    const float4* w1 = (const float4*)(Waff + G4 + 256);
    float s0 = 0.f, s1 = 0.f;
    #pragma unroll
    for (int i = lane; i < KIN / 4; i += 32) {
        float4 av = a[i], v0 = w0[i], v1 = w1[i];
        s0 = fmaf(av.x, v0.x, s0); s0 = fmaf(av.y, v0.y, s0);
        s0 = fmaf(av.z, v0.z, s0); s0 = fmaf(av.w, v0.w, s0);
        s1 = fmaf(av.x, v1.x, s1); s1 = fmaf(av.y, v1.y, s1);
        s1 = fmaf(av.z, v1.z, s1); s1 = fmaf(av.w, v1.w, s1);
    }
    #pragma unroll
    for (int o = 16; o > 0; o >>= 1) {
        s0 += __shfl_xor_sync(0xffffffffu, s0, o);
        s1 += __shfl_xor_sync(0xffffffffu, s1, o);
    }
    if (lane == 0) {
        g_sp[(size_t)warp * 2]     = s0 + baff[0];
        g_sp[(size_t)warp * 2 + 1] = s1 + baff[1];
    }
}

// ---------------- recurrence: R9 structure, t-sliced with gmem state handoff ----------------
struct RnnSmem {
    float hbuf[2][NB][H_];     // offset 0; double-buffered MASKED h (16B aligned)
    float part[2][128][NB];
    float tagc[3][RROWS];
    float waffh[2][H_];
    float maskS[NB][T_];
    float hstage[NB * JS];
    float scstage[8];
    float scp[2][8][8];
    int   pred[NB];
};

__device__ __forceinline__ float sigf(float x) {
    return __fdividef(1.f, 1.f + __expf(-x));
}
__device__ __forceinline__ float tanhfast(float x) {
    float e = __expf(2.f * x);
    return 1.f - __fdividef(2.f, e + 1.f);
}

__global__ void __cluster_dims__(CLUSTER, 1, 1) __launch_bounds__(256, 1)
rnn_kernel(const float* __restrict__ mask,
           const float* __restrict__ Whh,
           const float* __restrict__ Waff,
           float* __restrict__ out,
           int t0) {
    extern __shared__ unsigned char smem_raw[];
    RnnSmem& s = *reinterpret_cast<RnnSmem*>(smem_raw);

    const int tid = threadIdx.x;
    const uint32_t rank = ctarank_();
    const int cid = blockIdx.x >> 3;
    const int bbase = cid * NB;

    const int r = tid & 127;
    const int half = tid >> 7;
    const int grow = (r >> 5) * 256 + (int)rank * JS + (r & 31);

    ulonglong2 wreg2[32];
    {
        const ulonglong2* wsrc = (const ulonglong2*)(Whh + (size_t)grow * H_ + half * 128);
        #pragma unroll
        for (int i = 0; i < 32; ++i) wreg2[i] = wsrc[i];
    }

    for (int rr = tid; rr < RROWS; rr += 256) {
        int gr = (rr >> 5) * 256 + (int)rank * JS + (rr & 31);
        s.tagc[0][rr] = g_tagc[gr];
        s.tagc[1][rr] = g_tagc[G4 + gr];
        s.tagc[2][rr] = 0.f;
    }
    for (int i = tid; i < 2 * H_; i += 256) s.waffh[i >> 8][i & 255] = Waff[(i >> 8) * G4 + (i & 255)];
    // load carried h state into hbuf[0]  (t0 is even, so first step reads parity 0)
    for (int i = tid; i < NB * H_; i += 256)
        s.hbuf[0][i >> 8][i & 255] = g_h[(bbase + (i >> 8)) * H_ + (i & 255)];
    for (int i = tid; i < NB * T_; i += 256)
        s.maskS[i >> 9][i & 511] = mask[(size_t)(bbase + (i >> 9)) * T_ + (i & 511)];
    if (tid < NB) s.pred[tid] = g_pred[bbase + tid];
    __syncthreads();

    const int eb = tid >> 5, ej = tid & 31;    // phase-2 identity (tid < 128)
    float c_reg = 0.f;
    if (tid < 128) c_reg = g_c[(bbase + eb) * H_ + (int)rank * JS + ej];

    const int pdst = tid & 7;
    const int pchunk = tid >> 3;
    const int pe = pchunk * 4;
    const int peb = pe >> 5, pej = pe & 31;

    size_t gbase = 0;
    if (tid < 128)
        gbase = ((size_t)(bbase + eb) * T_) * G4 + (int)rank * JS + ej;
    float gpn[4];
    if (tid < 128) {
        #pragma unroll
        for (int g = 0; g < 4; ++g) gpn[g] = __ldg(&g_gp[gbase + (size_t)t0 * G4 + g * 256]);
    }
    const size_t spbase = (size_t)(bbase + (tid & 3)) * T_ * 2;
    float spn0 = 0.f, spn1 = 0.f;
    if (tid < NB) {
        spn0 = __ldg(&g_sp[spbase + (size_t)t0 * 2]);
        spn1 = __ldg(&g_sp[spbase + (size_t)t0 * 2 + 1]);
    }

    const int tend = t0 + TS_;
    for (int t = t0; t < tend; ++t) {
        const int par = t & 1;

        float gp[4];
        if (tid < 128) {
            #pragma unroll
            for (int g = 0; g < 4; ++g) gp[g] = gpn[g];
            if (t + 1 < T_) {
                const size_t gb = gbase + (size_t)(t + 1) * G4;
                #pragma unroll
                for (int g = 0; g < 4; ++g) gpn[g] = __ldg(&g_gp[gb + g * 256]);
            }
        }
        float sp0 = spn0, sp1 = spn1;
        if (tid < NB && t + 1 < T_) {
            spn0 = __ldg(&g_sp[spbase + (size_t)(t + 1) * 2]);
            spn1 = __ldg(&g_sp[spbase + (size_t)(t + 1) * 2 + 1]);
        }

        // ---- phase 1: matvec partials via packed f32x2 (reads hbuf[par]) ----
        float a2[NB];
        #pragma unroll
        for (int b = 0; b < NB; ++b) {
            const ulonglong2* x2 = (const ulonglong2*)&s.hbuf[par][b][half * 128];
            unsigned long long acc0 = 0ULL, acc1 = 0ULL;
            #pragma unroll
            for (int i = 0; i < 32; ++i) {
                ulonglong2 w = wreg2[i];
                ulonglong2 xv = x2[i];
                fma2(acc0, w.x, xv.x);
                fma2(acc1, w.y, xv.y);
            }
            float2 f0 = unpack64(acc0), f1 = unpack64(acc1);
            a2[b] = (f0.x + f0.y) + (f1.x + f1.y);
        }
        *(float4*)&s.part[half][r][0] = make_float4(a2[0], a2[1], a2[2], a2[3]);
        __syncthreads();   // A

        // ---- phase 2 (tid<128): gates, cell, masked h to stage, score partials ----
        if (tid < 128) {
            const int pd = s.pred[eb];
            float gate[4];
            #pragma unroll
            for (int g = 0; g < 4; ++g) {
                const int rr = g * 32 + ej;
                gate[g] = gp[g] + s.tagc[pd][rr] + s.part[0][rr][eb] + s.part[1][rr][eb];
            }
            float cn = sigf(gate[1]) * c_reg + sigf(gate[0]) * tanhfast(gate[2]);
            float hn = sigf(gate[3]) * tanhfast(cn);
            float mi = s.maskS[eb][t];
            c_reg = mi * cn + (1.f - mi) * c_reg;
            float hold = s.hbuf[par][eb][(int)rank * JS + ej];
            s.hstage[eb * JS + ej] = mi * hn + (1.f - mi) * hold;
            float p0 = hn * s.waffh[0][(int)rank * JS + ej];
            float p1 = hn * s.waffh[1][(int)rank * JS + ej];
            #pragma unroll
            for (int o = 16; o > 0; o >>= 1) {
                p0 += __shfl_xor_sync(0xffffffffu, p0, o);
                p1 += __shfl_xor_sync(0xffffffffu, p1, o);
            }
            if (ej == 0) {
                s.scstage[eb * 2]     = p0;
                s.scstage[eb * 2 + 1] = p1;
            }
        }
        __syncthreads();   // B

        // ---- push: vectorized remote stores ----
        {
            const uint4 hv = *(const uint4*)&s.hstage[pe];
            uint32_t daddr = (uint32_t)__cvta_generic_to_shared(
                &s.hbuf[par ^ 1][peb][(int)rank * JS + pej]);
            st_cluster_v4(daddr, (uint32_t)pdst, hv.x, hv.y, hv.z, hv.w);
            if (tid < 16) {
                const uint4 sv = *(const uint4*)&s.scstage[(tid >> 3) * 4];
                uint32_t saddr2 = (uint32_t)__cvta_generic_to_shared(
                    &s.scp[par][rank][(tid >> 3) * 4]);
                st_cluster_v4(saddr2, (uint32_t)pdst, sv.x, sv.y, sv.z, sv.w);
            }
        }
        cluster_sync_();   // C

        // ---- phase 3 (tid<4): sum score partials, pred, output ----
        if (tid < NB) {
            float s0 = sp0, s1 = sp1;
            #pragma unroll
            for (int src = 0; src < 8; ++src) {
                s0 += s.scp[par][src][tid * 2];
                s1 += s.scp[par][src][tid * 2 + 1];
            }
            s.pred[tid] = (s1 > s0) ? 1 : 0;
            if (rank == 0) {
                float mx = fmaxf(s0, s1);
                float lse = mx + __logf(__expf(s0 - mx) + __expf(s1 - mx));
                size_t o = ((size_t)(bbase + tid) * T_ + t) * 2;
                out[o]     = s0 - lse;
                out[o + 1] = s1 - lse;
            }
        }
    }

    // ---- state handoff: last push landed in hbuf[0] (tend-1 is odd) ----
    __syncthreads();
    if (tid < 128)
        g_c[(bbase + eb) * H_ + (int)rank * JS + ej] = c_reg;
    if (rank == 0) {
        for (int i = tid; i < NB * H_; i += 256)
            g_h[(bbase + (i >> 8)) * H_ + (i & 255)] = s.hbuf[0][i >> 8][i & 255];
        if (tid < NB) g_pred[bbase + tid] = s.pred[tid];
    }
    cluster_sync_();
}

// ---------------- launch: dual-stream overlap of gemm slices with rnn slices ----------------
extern "C" void kernel_launch(void* const* d_in, const int* in_sizes, int n_in,
                              void* d_out, int out_size) {
    const float* sents  = (const float*)d_in[0];
    const float* mask   = (const float*)d_in[1];
    const float* Wih    = (const float*)d_in[2];
    const float* Whh    = (const float*)d_in[3];
    const float* bih    = (const float*)d_in[4];
    const float* bhh    = (const float*)d_in[5];
    const float* Waff   = (const float*)d_in[6];
    const float* baff   = (const float*)d_in[7];
    const float* tag_em = (const float*)d_in[8];
    float* out = (float*)d_out;

    static cudaStream_t s2 = nullptr;
    static cudaEvent_t evC = nullptr, ev1 = nullptr, ev2 = nullptr, ev3 = nullptr;
    if (s2 == nullptr) {
        cudaStreamCreateWithFlags(&s2, cudaStreamNonBlocking);
        cudaEventCreateWithFlags(&evC, cudaEventDisableTiming);
        cudaEventCreateWithFlags(&ev1, cudaEventDisableTiming);
        cudaEventCreateWithFlags(&ev2, cudaEventDisableTiming);
        cudaEventCreateWithFlags(&ev3, cudaEventDisableTiming);
    }

    cudaFuncSetAttribute(gemm_kernel, cudaFuncAttributeMaxDynamicSharedMemorySize, GSM_TOTAL);
    cudaFuncSetAttribute(rnn_kernel, cudaFuncAttributeMaxDynamicSharedMemorySize,
                         (int)sizeof(RnnSmem));

    // main stream: prep + spre + gemm slice 0
    conv_fused_kernel<<<NBLK_A + NBLK_B + NBLK_P + NBLK_S, 256>>>(sents, Wih, bih, bhh, tag_em);
    cudaEventRecord(evC, 0);
    spre_kernel<<<(B_ * T_) / 8, 256>>>(sents, Waff, baff);
    gemm_kernel<<<dim3(G4 / 128, 64), 256, GSM_TOTAL>>>(0);

    // side stream: gemm slices 1-3 (depend only on conv)
    cudaStreamWaitEvent(s2, evC, 0);
    gemm_kernel<<<dim3(G4 / 128, 64), 256, GSM_TOTAL, s2>>>(1);
    cudaEventRecord(ev1, s2);
    gemm_kernel<<<dim3(G4 / 128, 64), 256, GSM_TOTAL, s2>>>(2);
    cudaEventRecord(ev2, s2);
    gemm_kernel<<<dim3(G4 / 128, 64), 256, GSM_TOTAL, s2>>>(3);
    cudaEventRecord(ev3, s2);

    // main stream: rnn slices, each gated on its gemm slice
    rnn_kernel<<<16 * CLUSTER, 256, sizeof(RnnSmem)>>>(mask, Whh, Waff, out, 0);
    cudaStreamWaitEvent(0, ev1, 0);
    rnn_kernel<<<16 * CLUSTER, 256, sizeof(RnnSmem)>>>(mask, Whh, Waff, out, 128);
    cudaStreamWaitEvent(0, ev2, 0);
    rnn_kernel<<<16 * CLUSTER, 256, sizeof(RnnSmem)>>>(mask, Whh, Waff, out, 256);
    cudaStreamWaitEvent(0, ev3, 0);
    rnn_kernel<<<16 * CLUSTER, 256, sizeof(RnnSmem)>>>(mask, Whh, Waff, out, 384);
}

// round 15
// speedup vs baseline: 1.0016x; 1.0008x over previous
#include <cuda_runtime.h>
#include <cuda_bf16.h>
#include <cstdint>
#include <cstddef>

#define B_    64
#define T_    512
#define TS_   128     // rnn/gemm time slice
#define H_    256
#define G4    1024
#define KIN   768
#define CLUSTER 8
#define NB    4
#define JS    32
#define RROWS 128

#define KC    32
#define NCH   24
#define NSTG  2
#define ROWB  80
#define TILE_B (128 * ROWB)
#define STG_B  (4 * TILE_B)
#define GSM_TOTAL (NSTG * STG_B)   // 81920

// ---------------- scratch ----------------
__device__ float g_gp[(size_t)B_ * T_ * G4];
__device__ float g_sp[B_ * T_ * 2];
__device__ float g_bias[G4];
__device__ float g_tagc[3 * G4];
__device__ float g_h[B_ * H_];
__device__ float g_c[B_ * H_];
__device__ int   g_pred[B_];
__device__ __align__(16) __nv_bfloat16 g_Ahi[(size_t)B_ * T_ * KIN];
__device__ __align__(16) __nv_bfloat16 g_Alo[(size_t)B_ * T_ * KIN];
__device__ __align__(16) __nv_bfloat16 g_Bhi[G4 * KIN];
__device__ __align__(16) __nv_bfloat16 g_Blo[G4 * KIN];

// ---------------- PTX helpers (base sm_103 only) ----------------
__device__ __forceinline__ uint32_t smem_u32(const void* p) {
    uint32_t a;
    asm("{ .reg .u64 t; cvta.to.shared.u64 t, %1; cvt.u32.u64 %0, t; }" : "=r"(a) : "l"(p));
    return a;
}
__device__ __forceinline__ uint32_t ctarank_() {
    uint32_t r; asm("mov.u32 %0, %%cluster_ctarank;" : "=r"(r)); return r;
}
__device__ __forceinline__ void cluster_sync_() {
    asm volatile("barrier.cluster.arrive.aligned;\n\tbarrier.cluster.wait.aligned;" ::: "memory");
}
__device__ __forceinline__ void st_cluster_v4(uint32_t saddr, uint32_t dst,
                                              uint32_t a, uint32_t b,
                                              uint32_t c, uint32_t d) {
    asm volatile(
        "{\n\t.reg .b32 ra;\n\t"
        "mapa.shared::cluster.u32 ra, %0, %1;\n\t"
        "st.shared::cluster.v4.b32 [ra], {%2,%3,%4,%5};\n\t}"
        :: "r"(saddr), "r"(dst), "r"(a), "r"(b), "r"(c), "r"(d) : "memory");
}
__device__ __forceinline__ void cp16(uint32_t dst, const void* src) {
    asm volatile("cp.async.cg.shared.global [%0], [%1], 16;" :: "r"(dst), "l"(src));
}
#define CP_COMMIT() asm volatile("cp.async.commit_group;" ::: "memory")
#define CP_WAIT1()  asm volatile("cp.async.wait_group 1;" ::: "memory")
#define CP_WAIT0()  asm volatile("cp.async.wait_group 0;" ::: "memory")

__device__ __forceinline__ void ldsm4(uint32_t* r, uint32_t addr) {
    asm volatile("ldmatrix.sync.aligned.m8n8.x4.shared.b16 {%0,%1,%2,%3}, [%4];"
                 : "=r"(r[0]), "=r"(r[1]), "=r"(r[2]), "=r"(r[3]) : "r"(addr));
}
__device__ __forceinline__ void mma16816(float* c, const uint32_t* a, const uint32_t* b) {
    asm volatile(
        "mma.sync.aligned.m16n8k16.row.col.f32.bf16.bf16.f32 "
        "{%0,%1,%2,%3}, {%4,%5,%6,%7}, {%8,%9}, {%0,%1,%2,%3};"
        : "+f"(c[0]), "+f"(c[1]), "+f"(c[2]), "+f"(c[3])
        : "r"(a[0]), "r"(a[1]), "r"(a[2]), "r"(a[3]), "r"(b[0]), "r"(b[1]));
}
__device__ __forceinline__ void fma2(unsigned long long& d, unsigned long long a,
                                     unsigned long long b) {
    asm("fma.rn.f32x2 %0, %1, %2, %0;" : "+l"(d) : "l"(a), "l"(b));
}
__device__ __forceinline__ float2 unpack64(unsigned long long v) {
    float2 r;
    asm("mov.b64 {%0, %1}, %2;" : "=f"(r.x), "=f"(r.y) : "l"(v));
    return r;
}

// ---------------- fused prep: convA + convB + bias/tagc + rnn state init ----------------
#define NBLK_A 24576
#define NBLK_B 768
#define NBLK_P 4
#define NBLK_S 129
__global__ __launch_bounds__(256) void conv_fused_kernel(
    const float* __restrict__ A, const float* __restrict__ Wih,
    const float* __restrict__ bih, const float* __restrict__ bhh,
    const float* __restrict__ tag_em) {
    const int bid = blockIdx.x;
    if (bid < NBLK_A) {
        size_t i4 = (size_t)bid * 256 + threadIdx.x;
        float4 v = *(const float4*)(A + i4 * 4);
        __nv_bfloat16 hx = __float2bfloat16_rn(v.x), hy = __float2bfloat16_rn(v.y);
        __nv_bfloat16 hz = __float2bfloat16_rn(v.z), hw = __float2bfloat16_rn(v.w);
        __nv_bfloat16 lx = __float2bfloat16_rn(v.x - __bfloat162float(hx));
        __nv_bfloat16 ly = __float2bfloat16_rn(v.y - __bfloat162float(hy));
        __nv_bfloat16 lz = __float2bfloat16_rn(v.z - __bfloat162float(hz));
        __nv_bfloat16 lw = __float2bfloat16_rn(v.w - __bfloat162float(hw));
        __nv_bfloat16 hv[4] = {hx, hy, hz, hw};
        __nv_bfloat16 lv[4] = {lx, ly, lz, lw};
        ((uint2*)g_Ahi)[i4] = *(uint2*)hv;
        ((uint2*)g_Alo)[i4] = *(uint2*)lv;
    } else if (bid < NBLK_A + NBLK_B) {
        size_t i4 = (size_t)(bid - NBLK_A) * 256 + threadIdx.x;
        size_t e = i4 * 4;
        int n = (int)(e / KIN), k = (int)(e % KIN);
        float4 v = *(const float4*)(Wih + (size_t)n * 800 + 32 + k);
        __nv_bfloat16 hx = __float2bfloat16_rn(v.x), hy = __float2bfloat16_rn(v.y);
        __nv_bfloat16 hz = __float2bfloat16_rn(v.z), hw = __float2bfloat16_rn(v.w);
        __nv_bfloat16 lx = __float2bfloat16_rn(v.x - __bfloat162float(hx));
        __nv_bfloat16 ly = __float2bfloat16_rn(v.y - __bfloat162float(hy));
        __nv_bfloat16 lz = __float2bfloat16_rn(v.z - __bfloat162float(hz));
        __nv_bfloat16 lw = __float2bfloat16_rn(v.w - __bfloat162float(hw));
        __nv_bfloat16 hv[4] = {hx, hy, hz, hw};
        __nv_bfloat16 lv[4] = {lx, ly, lz, lw};
        ((uint2*)g_Bhi)[i4] = *(uint2*)hv;
        ((uint2*)g_Blo)[i4] = *(uint2*)lv;
    } else if (bid < NBLK_A + NBLK_B + NBLK_P) {
        int n = (bid - NBLK_A - NBLK_B) * 256 + threadIdx.x;
        if (n >= G4) return;
        g_bias[n] = bih[n] + bhh[n];
        float t0 = 0.f, t1 = 0.f;
        #pragma unroll
        for (int e = 0; e < 32; ++e) {
            float w = Wih[n * 800 + e];
            t0 = fmaf(tag_em[e], w, t0);
            t1 = fmaf(tag_em[32 + e], w, t1);
        }
        g_tagc[n] = t0;
        g_tagc[G4 + n] = t1;
        g_tagc[2 * G4 + n] = 0.f;
    } else {
        int sid = bid - NBLK_A - NBLK_B - NBLK_P;
        if (sid < 64) g_h[sid * 256 + threadIdx.x] = 0.f;
        else if (sid < 128) g_c[(sid - 64) * 256 + threadIdx.x] = 0.f;
        else if (threadIdx.x < B_) g_pred[threadIdx.x] = 2;
    }
}

// ---------------- HMMA GEMM, t-sliced: bm = blockIdx.y*4 + q ----------------
__global__ __launch_bounds__(256, 2) void gemm_kernel(int q) {
    extern __shared__ char smem[];
    const uint32_t sb = smem_u32(smem);
    const int tid = threadIdx.x;
    const int wid = tid >> 5, lane = tid & 31;
    const int bn = blockIdx.x, bm = blockIdx.y * 4 + q;
    const int m0 = bm * 128, n0 = bn * 128;
    const int wm = (wid & 1) * 64;
    const int wn = (wid >> 1) * 32;

    const __nv_bfloat16* srcp[8];
    uint32_t dsto[8];
    #pragma unroll
    for (int i = 0; i < 8; ++i) {
        int id = tid + i * 256;
        int tile = id >> 9, rem = id & 511;
        int row = rem >> 2, c4 = rem & 3;
        const __nv_bfloat16* base =
            (tile == 0) ? g_Ahi + (size_t)m0 * KIN :
            (tile == 1) ? g_Alo + (size_t)m0 * KIN :
            (tile == 2) ? g_Bhi + (size_t)n0 * KIN :
                          g_Blo + (size_t)n0 * KIN;
        srcp[i] = base + (size_t)row * KIN + c4 * 8;
        dsto[i] = (uint32_t)(tile * TILE_B + row * ROWB + c4 * 16);
    }

    float acc[4][4][4];
    #pragma unroll
    for (int a = 0; a < 4; ++a)
        #pragma unroll
        for (int b = 0; b < 4; ++b)
            #pragma unroll
            for (int qq = 0; qq < 4; ++qq) acc[a][b][qq] = 0.f;

    const uint32_t aoff = (uint32_t)((wm + (lane & 15)) * ROWB + (lane >> 4) * 16);
    const int brow = ((lane >> 4) & 1) * 8 + (lane & 7);
    const uint32_t boff = (uint32_t)((wn + brow) * ROWB + ((lane >> 3) & 1) * 16);

    #pragma unroll
    for (int i = 0; i < 8; ++i) cp16(sb + dsto[i], srcp[i]);
    CP_COMMIT();

    for (int c = 0; c < NCH; ++c) {
        if (c + 1 < NCH) {
            uint32_t stg = sb + (uint32_t)((c + 1) & 1) * STG_B;
            #pragma unroll
            for (int i = 0; i < 8; ++i) cp16(stg + dsto[i], srcp[i] + (c + 1) * KC);
            CP_COMMIT();
            CP_WAIT1();
        } else {
            CP_WAIT0();
        }
        __syncthreads();

        const uint32_t sbase = sb + (uint32_t)(c & 1) * STG_B;
        const uint32_t sAhi = sbase, sAlo = sbase + TILE_B;
        const uint32_t sBhi = sbase + 2 * TILE_B, sBlo = sbase + 3 * TILE_B;

        #pragma unroll
        for (int ks = 0; ks < 2; ++ks) {
            const uint32_t ko = ks * 32;
            uint32_t ah[4][4], bh[2][4], bl[2][4];
            #pragma unroll
            for (int mi = 0; mi < 4; ++mi) ldsm4(ah[mi], sAhi + aoff + mi * 16 * ROWB + ko);
            #pragma unroll
            for (int nj = 0; nj < 2; ++nj) ldsm4(bh[nj], sBhi + boff + nj * 16 * ROWB + ko);
            #pragma unroll
            for (int mi = 0; mi < 4; ++mi)
                #pragma unroll
                for (int ni = 0; ni < 4; ++ni)
                    mma16816(acc[mi][ni], ah[mi], &bh[ni >> 1][(ni & 1) * 2]);
            #pragma unroll
            for (int nj = 0; nj < 2; ++nj) ldsm4(bl[nj], sBlo + boff + nj * 16 * ROWB + ko);
            #pragma unroll
            for (int mi = 0; mi < 4; ++mi)
                #pragma unroll
                for (int ni = 0; ni < 4; ++ni)
                    mma16816(acc[mi][ni], ah[mi], &bl[ni >> 1][(ni & 1) * 2]);
            #pragma unroll
            for (int mi = 0; mi < 4; ++mi) ldsm4(ah[mi], sAlo + aoff + mi * 16 * ROWB + ko);
            #pragma unroll
            for (int mi = 0; mi < 4; ++mi)
                #pragma unroll
                for (int ni = 0; ni < 4; ++ni)
                    mma16816(acc[mi][ni], ah[mi], &bh[ni >> 1][(ni & 1) * 2]);
        }
        __syncthreads();
    }

    const int rowb2 = lane >> 2, col2 = (lane & 3) * 2;
    #pragma unroll
    for (int mi = 0; mi < 4; ++mi) {
        const int gr = m0 + wm + mi * 16 + rowb2;
        #pragma unroll
        for (int ni = 0; ni < 4; ++ni) {
            const int gc = n0 + wn + ni * 8 + col2;
            float b0v = __ldg(&g_bias[gc]), b1v = __ldg(&g_bias[gc + 1]);
            float2 v0 = make_float2(acc[mi][ni][0] + b0v, acc[mi][ni][1] + b1v);
            float2 v1 = make_float2(acc[mi][ni][2] + b0v, acc[mi][ni][3] + b1v);
            *(float2*)&g_gp[(size_t)gr * G4 + gc] = v0;
            *(float2*)&g_gp[(size_t)(gr + 8) * G4 + gc] = v1;
        }
    }
}

// ---------------- score_pre ----------------
__global__ __launch_bounds__(256) void spre_kernel(const float* __restrict__ sents,
                                                   const float* __restrict__ Waff,
                                                   const float* __restrict__ baff) {
    int warp = (blockIdx.x * 256 + threadIdx.x) >> 5;
    int lane = threadIdx.x & 31;
    if (warp >= B_ * T_) return;
    const float4* a  = (const float4*)(sents + (size_t)warp * KIN);
    const float4* w0 = (const float4*)(Waff + 256);
    const float4* w1 = (const float4*)(Waff + G4 + 256);
    float s0 = 0.f, s1 = 0.f;
    #pragma unroll
    for (int i = lane; i < KIN / 4; i += 32) {
        float4 av = a[i], v0 = w0[i], v1 = w1[i];
        s0 = fmaf(av.x, v0.x, s0); s0 = fmaf(av.y, v0.y, s0);
        s0 = fmaf(av.z, v0.z, s0); s0 = fmaf(av.w, v0.w, s0);
        s1 = fmaf(av.x, v1.x, s1); s1 = fmaf(av.y, v1.y, s1);
        s1 = fmaf(av.z, v1.z, s1); s1 = fmaf(av.w, v1.w, s1);
    }
    #pragma unroll
    for (int o = 16; o > 0; o >>= 1) {
        s0 += __shfl_xor_sync(0xffffffffu, s0, o);
        s1 += __shfl_xor_sync(0xffffffffu, s1, o);
    }
    if (lane == 0) {
        g_sp[(size_t)warp * 2]     = s0 + baff[0];
        g_sp[(size_t)warp * 2 + 1] = s1 + baff[1];
    }
}

// ---------------- recurrence: R9 structure, t-sliced with gmem state handoff ----------------
struct RnnSmem {
    float hbuf[2][NB][H_];     // offset 0; double-buffered MASKED h (16B aligned)
    float part[2][128][NB];
    float tagc[3][RROWS];
    float waffh[2][H_];
    float maskS[NB][T_];
    float hstage[NB * JS];
    float scstage[8];
    float scp[2][8][8];
    int   pred[NB];
};

__device__ __forceinline__ float sigf(float x) {
    return __fdividef(1.f, 1.f + __expf(-x));
}
__device__ __forceinline__ float tanhfast(float x) {
    float e = __expf(2.f * x);
    return 1.f - __fdividef(2.f, e + 1.f);
}

__global__ void __cluster_dims__(CLUSTER, 1, 1) __launch_bounds__(256, 1)
rnn_kernel(const float* __restrict__ mask,
           const float* __restrict__ Whh,
           const float* __restrict__ Waff,
           float* __restrict__ out,
           int t0) {
    extern __shared__ unsigned char smem_raw[];
    RnnSmem& s = *reinterpret_cast<RnnSmem*>(smem_raw);

    const int tid = threadIdx.x;
    const uint32_t rank = ctarank_();
    const int cid = blockIdx.x >> 3;
    const int bbase = cid * NB;

    const int r = tid & 127;
    const int half = tid >> 7;
    const int grow = (r >> 5) * 256 + (int)rank * JS + (r & 31);

    ulonglong2 wreg2[32];
    {
        const ulonglong2* wsrc = (const ulonglong2*)(Whh + (size_t)grow * H_ + half * 128);
        #pragma unroll
        for (int i = 0; i < 32; ++i) wreg2[i] = wsrc[i];
    }

    for (int rr = tid; rr < RROWS; rr += 256) {
        int gr = (rr >> 5) * 256 + (int)rank * JS + (rr & 31);
        s.tagc[0][rr] = g_tagc[gr];
        s.tagc[1][rr] = g_tagc[G4 + gr];
        s.tagc[2][rr] = 0.f;
    }
    for (int i = tid; i < 2 * H_; i += 256) s.waffh[i >> 8][i & 255] = Waff[(i >> 8) * G4 + (i & 255)];
    // load carried h state into hbuf[0]  (t0 is even, so first step reads parity 0)
    for (int i = tid; i < NB * H_; i += 256)
        s.hbuf[0][i >> 8][i & 255] = g_h[(bbase + (i >> 8)) * H_ + (i & 255)];
    for (int i = tid; i < NB * T_; i += 256)
        s.maskS[i >> 9][i & 511] = mask[(size_t)(bbase + (i >> 9)) * T_ + (i & 511)];
    if (tid < NB) s.pred[tid] = g_pred[bbase + tid];
    __syncthreads();

    const int eb = tid >> 5, ej = tid & 31;    // phase-2 identity (tid < 128)
    float c_reg = 0.f;
    if (tid < 128) c_reg = g_c[(bbase + eb) * H_ + (int)rank * JS + ej];

    const int pdst = tid & 7;
    const int pchunk = tid >> 3;
    const int pe = pchunk * 4;
    const int peb = pe >> 5, pej = pe & 31;

    size_t gbase = 0;
    if (tid < 128)
        gbase = ((size_t)(bbase + eb) * T_) * G4 + (int)rank * JS + ej;
    float gpn[4];
    if (tid < 128) {
        #pragma unroll
        for (int g = 0; g < 4; ++g) gpn[g] = __ldg(&g_gp[gbase + (size_t)t0 * G4 + g * 256]);
    }
    const size_t spbase = (size_t)(bbase + (tid & 3)) * T_ * 2;
    float spn0 = 0.f, spn1 = 0.f;
    if (tid < NB) {
        spn0 = __ldg(&g_sp[spbase + (size_t)t0 * 2]);
        spn1 = __ldg(&g_sp[spbase + (size_t)t0 * 2 + 1]);
    }

    const int tend = t0 + TS_;
    for (int t = t0; t < tend; ++t) {
        const int par = t & 1;

        float gp[4];
        if (tid < 128) {
            #pragma unroll
            for (int g = 0; g < 4; ++g) gp[g] = gpn[g];
            if (t + 1 < T_) {
                const size_t gb = gbase + (size_t)(t + 1) * G4;
                #pragma unroll
                for (int g = 0; g < 4; ++g) gpn[g] = __ldg(&g_gp[gb + g * 256]);
            }
        }
        float sp0 = spn0, sp1 = spn1;
        if (tid < NB && t + 1 < T_) {
            spn0 = __ldg(&g_sp[spbase + (size_t)(t + 1) * 2]);
            spn1 = __ldg(&g_sp[spbase + (size_t)(t + 1) * 2 + 1]);
        }

        // ---- phase 1: matvec partials via packed f32x2 (reads hbuf[par]) ----
        float a2[NB];
        #pragma unroll
        for (int b = 0; b < NB; ++b) {
            const ulonglong2* x2 = (const ulonglong2*)&s.hbuf[par][b][half * 128];
            unsigned long long acc0 = 0ULL, acc1 = 0ULL;
            #pragma unroll
            for (int i = 0; i < 32; ++i) {
                ulonglong2 w = wreg2[i];
                ulonglong2 xv = x2[i];
                fma2(acc0, w.x, xv.x);
                fma2(acc1, w.y, xv.y);
            }
            float2 f0 = unpack64(acc0), f1 = unpack64(acc1);
            a2[b] = (f0.x + f0.y) + (f1.x + f1.y);
        }
        *(float4*)&s.part[half][r][0] = make_float4(a2[0], a2[1], a2[2], a2[3]);
        __syncthreads();   // A

        // ---- phase 2 (tid<128): gates, cell, masked h to stage, score partials ----
        if (tid < 128) {
            const int pd = s.pred[eb];
            float gate[4];
            #pragma unroll
            for (int g = 0; g < 4; ++g) {
                const int rr = g * 32 + ej;
                gate[g] = gp[g] + s.tagc[pd][rr] + s.part[0][rr][eb] + s.part[1][rr][eb];
            }
            float cn = sigf(gate[1]) * c_reg + sigf(gate[0]) * tanhfast(gate[2]);
            float hn = sigf(gate[3]) * tanhfast(cn);
            float mi = s.maskS[eb][t];
            c_reg = mi * cn + (1.f - mi) * c_reg;
            float hold = s.hbuf[par][eb][(int)rank * JS + ej];
            s.hstage[eb * JS + ej] = mi * hn + (1.f - mi) * hold;
            float p0 = hn * s.waffh[0][(int)rank * JS + ej];
            float p1 = hn * s.waffh[1][(int)rank * JS + ej];
            #pragma unroll
            for (int o = 16; o > 0; o >>= 1) {
                p0 += __shfl_xor_sync(0xffffffffu, p0, o);
                p1 += __shfl_xor_sync(0xffffffffu, p1, o);
            }
            if (ej == 0) {
                s.scstage[eb * 2]     = p0;
                s.scstage[eb * 2 + 1] = p1;
            }
        }
        __syncthreads();   // B

        // ---- push: vectorized remote stores ----
        {
            const uint4 hv = *(const uint4*)&s.hstage[pe];
            uint32_t daddr = (uint32_t)__cvta_generic_to_shared(
                &s.hbuf[par ^ 1][peb][(int)rank * JS + pej]);
            st_cluster_v4(daddr, (uint32_t)pdst, hv.x, hv.y, hv.z, hv.w);
            if (tid < 16) {
                const uint4 sv = *(const uint4*)&s.scstage[(tid >> 3) * 4];
                uint32_t saddr2 = (uint32_t)__cvta_generic_to_shared(
                    &s.scp[par][rank][(tid >> 3) * 4]);
                st_cluster_v4(saddr2, (uint32_t)pdst, sv.x, sv.y, sv.z, sv.w);
            }
        }
        cluster_sync_();   // C

        // ---- phase 3 (tid<4): sum score partials, pred, output ----
        if (tid < NB) {
            float s0 = sp0, s1 = sp1;
            #pragma unroll
            for (int src = 0; src < 8; ++src) {
                s0 += s.scp[par][src][tid * 2];
                s1 += s.scp[par][src][tid * 2 + 1];
            }
            s.pred[tid] = (s1 > s0) ? 1 : 0;
            if (rank == 0) {
                float mx = fmaxf(s0, s1);
                float lse = mx + __logf(__expf(s0 - mx) + __expf(s1 - mx));
                size_t o = ((size_t)(bbase + tid) * T_ + t) * 2;
                out[o]     = s0 - lse;
                out[o + 1] = s1 - lse;
            }
        }
    }

    // ---- state handoff: last push landed in hbuf[0] (tend-1 is odd) ----
    __syncthreads();
    if (tid < 128)
        g_c[(bbase + eb) * H_ + (int)rank * JS + ej] = c_reg;
    if (rank == 0) {
        for (int i = tid; i < NB * H_; i += 256)
            g_h[(bbase + (i >> 8)) * H_ + (i & 255)] = s.hbuf[0][i >> 8][i & 255];
        if (tid < NB) g_pred[bbase + tid] = s.pred[tid];
    }
    cluster_sync_();
}

// ---------------- launch: dual-stream overlap of gemm slices with rnn slices ----------------
extern "C" void kernel_launch(void* const* d_in, const int* in_sizes, int n_in,
                              void* d_out, int out_size) {
    const float* sents  = (const float*)d_in[0];
    const float* mask   = (const float*)d_in[1];
    const float* Wih    = (const float*)d_in[2];
    const float* Whh    = (const float*)d_in[3];
    const float* bih    = (const float*)d_in[4];
    const float* bhh    = (const float*)d_in[5];
    const float* Waff   = (const float*)d_in[6];
    const float* baff   = (const float*)d_in[7];
    const float* tag_em = (const float*)d_in[8];
    float* out = (float*)d_out;

    static cudaStream_t s2 = nullptr;
    static cudaEvent_t evC = nullptr, ev1 = nullptr, ev2 = nullptr, ev3 = nullptr;
    if (s2 == nullptr) {
        cudaStreamCreateWithFlags(&s2, cudaStreamNonBlocking);
        cudaEventCreateWithFlags(&evC, cudaEventDisableTiming);
        cudaEventCreateWithFlags(&ev1, cudaEventDisableTiming);
        cudaEventCreateWithFlags(&ev2, cudaEventDisableTiming);
        cudaEventCreateWithFlags(&ev3, cudaEventDisableTiming);
    }

    cudaFuncSetAttribute(gemm_kernel, cudaFuncAttributeMaxDynamicSharedMemorySize, GSM_TOTAL);
    cudaFuncSetAttribute(rnn_kernel, cudaFuncAttributeMaxDynamicSharedMemorySize,
                         (int)sizeof(RnnSmem));

    // main stream: prep + spre + gemm slice 0
    conv_fused_kernel<<<NBLK_A + NBLK_B + NBLK_P + NBLK_S, 256>>>(sents, Wih, bih, bhh, tag_em);
    cudaEventRecord(evC, 0);
    spre_kernel<<<(B_ * T_) / 8, 256>>>(sents, Waff, baff);
    gemm_kernel<<<dim3(G4 / 128, 64), 256, GSM_TOTAL>>>(0);

    // side stream: gemm slices 1-3 (depend only on conv)
    cudaStreamWaitEvent(s2, evC, 0);
    gemm_kernel<<<dim3(G4 / 128, 64), 256, GSM_TOTAL, s2>>>(1);
    cudaEventRecord(ev1, s2);
    gemm_kernel<<<dim3(G4 / 128, 64), 256, GSM_TOTAL, s2>>>(2);
    cudaEventRecord(ev2, s2);
    gemm_kernel<<<dim3(G4 / 128, 64), 256, GSM_TOTAL, s2>>>(3);
    cudaEventRecord(ev3, s2);

    // main stream: rnn slices, each gated on its gemm slice
    rnn_kernel<<<16 * CLUSTER, 256, sizeof(RnnSmem)>>>(mask, Whh, Waff, out, 0);
    cudaStreamWaitEvent(0, ev1, 0);
    rnn_kernel<<<16 * CLUSTER, 256, sizeof(RnnSmem)>>>(mask, Whh, Waff, out, 128);
    cudaStreamWaitEvent(0, ev2, 0);
    rnn_kernel<<<16 * CLUSTER, 256, sizeof(RnnSmem)>>>(mask, Whh, Waff, out, 256);
    cudaStreamWaitEvent(0, ev3, 0);
    rnn_kernel<<<16 * CLUSTER, 256, sizeof(RnnSmem)>>>(mask, Whh, Waff, out, 384);
}